// round 13
// baseline (speedup 1.0000x reference)
#include <cuda_runtime.h>
#include <cuda_bf16.h>
#include <stdint.h>

#define N_NODES 10000
#define N_EDGES 100000
#define HIDDEN  128
#define WN      1600
#define IN_DIM  56
#define NT      13
#define EPC     192                            // edges per CTA (both big kernels)
#define M_TILES ((N_EDGES + EPC - 1) / EPC)    // 521

// ---- scratch (static __device__; aligned for cp.async 16B) ----
__device__ __align__(256) __nv_bfloat16 g_Hhi[(size_t)N_EDGES * HIDDEN];
__device__ __align__(256) __nv_bfloat16 g_Hlo[(size_t)N_EDGES * HIDDEN];
__device__ __align__(256) uint4 g_B2pk[NT * 4096];   // packed fc2 fragments
__device__ __align__(256) uint4 g_B1pk[4096];        // packed fc1 fragments
__device__ __align__(256) float g_num[(size_t)N_NODES * IN_DIM];
__device__ __align__(256) float g_cnt[N_NODES];
__device__ __align__(256) float g_stats[72];

// ==================================================================
// PTX helpers
// ==================================================================
__device__ __forceinline__ uint32_t smem_u32(const void* p) {
    uint32_t a;
    asm("{ .reg .u64 t; cvta.to.shared.u64 t, %1; cvt.u32.u64 %0, t; }"
        : "=r"(a) : "l"(p));
    return a;
}
__device__ __forceinline__ void mma16816(float* c, const uint32_t* a,
                                         uint32_t b0, uint32_t b1) {
    asm volatile(
        "mma.sync.aligned.m16n8k16.row.col.f32.bf16.bf16.f32 "
        "{%0,%1,%2,%3}, {%4,%5,%6,%7}, {%8,%9}, {%0,%1,%2,%3};"
        : "+f"(c[0]), "+f"(c[1]), "+f"(c[2]), "+f"(c[3])
        : "r"(a[0]), "r"(a[1]), "r"(a[2]), "r"(a[3]), "r"(b0), "r"(b1));
}
__device__ __forceinline__ void cp16(uint32_t dst, const void* src) {
    asm volatile("cp.async.cg.shared.global [%0], [%1], 16;" :: "r"(dst), "l"(src));
}
#define CP_COMMIT() asm volatile("cp.async.commit_group;" ::: "memory")
#define CP_WAIT0()  asm volatile("cp.async.wait_group 0;" ::: "memory")
#define CP_WAIT1()  asm volatile("cp.async.wait_group 1;" ::: "memory")

__device__ __forceinline__ void split_pair(float v0, float v1,
                                           uint32_t& hi, uint32_t& lo) {
    __nv_bfloat16 h0 = __float2bfloat16(v0), h1 = __float2bfloat16(v1);
    hi = (uint32_t)__bfloat16_as_ushort(h0)
       | ((uint32_t)__bfloat16_as_ushort(h1) << 16);
    __nv_bfloat16 l0 = __float2bfloat16(v0 - __bfloat162float(h0));
    __nv_bfloat16 l1 = __float2bfloat16(v1 - __bfloat162float(h1));
    lo = (uint32_t)__bfloat16_as_ushort(l0)
       | ((uint32_t)__bfloat16_as_ushort(l1) << 16);
}

// ==================================================================
// zero accumulators (every replay)
// ==================================================================
__global__ void zero_kernel() {
    int i = blockIdx.x * blockDim.x + threadIdx.x;
    const int t0 = N_NODES * IN_DIM;
    const int t1 = t0 + N_NODES;
    const int t2 = t1 + 72;
    if (i < t0)       g_num[i] = 0.f;
    else if (i < t1)  g_cnt[i - t0] = 0.f;
    else if (i < t2)  g_stats[i - t1] = 0.f;
}

// ==================================================================
// pack W^T into fragment-major hi/lo uint4s (proven layout)
// DESTINATION IS THE GLOBAL SYMBOL, REFERENCED IN DEVICE CODE ONLY
// (host-passing a __device__ array silently writes host RAM via ATS)
// idx = ((nt*16 + n8)*8 + ks)*32 + lane
// n = nt*128 + n8*8 + lane/4 ; k = ks*16 + (lane%4)*2
// uint4 = { hi(k,k+1), hi(k+8,k+9), lo(k,k+1), lo(k+8,k+9) }
// ==================================================================
template<bool IS_B1>
__global__ void prepB_kernel(const float* __restrict__ src) {
    const int ntiles = IS_B1 ? 1 : NT;
    const int nvalid = IS_B1 ? 128 : WN;
    const int ld     = IS_B1 ? 128 : WN;
    uint4* dst = IS_B1 ? g_B1pk : g_B2pk;     // device-code symbol ref: valid
    int idx = blockIdx.x * blockDim.x + threadIdx.x;
    if (idx >= ntiles * 4096) return;
    int lane = idx & 31;
    int ks   = (idx >> 5) & 7;
    int n8   = (idx >> 8) & 15;
    int nt   = idx >> 12;
    int n = nt * 128 + n8 * 8 + (lane >> 2);
    int k = ks * 16 + (lane & 3) * 2;
    float v0 = 0.f, v1 = 0.f, v2 = 0.f, v3 = 0.f;
    if (n < nvalid) {
        v0 = src[(size_t)k * ld + n];
        v1 = src[(size_t)(k + 1) * ld + n];
        v2 = src[(size_t)(k + 8) * ld + n];
        v3 = src[(size_t)(k + 9) * ld + n];
    }
    uint32_t h01, l01, h23, l23;
    split_pair(v0, v1, h01, l01);
    split_pair(v2, v3, h23, l23);
    dst[idx] = make_uint4(h01, h23, l01, l23);
}

// ==================================================================
// GEMM1 (HMMA split-bf16): H = relu(edge_attr@fc1+b1) -> g_Hhi/g_Hlo
// 384 threads, 192 edges/CTA, quad accumulator chains
// ==================================================================
#define SA_ST   132
#define G1_SA   0                       // 192*132*4 = 101376
#define G1_BPK  101376                  // 65536
#define G1_BIAS 166912                  // 512
#define G1_SMEM 167424

__global__ void __launch_bounds__(384, 1)
sgemm1_mma_kernel(const float* __restrict__ edge_attr,
                  const float* __restrict__ fc1_b) {
    extern __shared__ char smem[];
    const uint32_t sb = smem_u32(smem);
    const int tid = threadIdx.x, warp = tid >> 5, lane = tid & 31;
    const int gid = lane >> 2, qid = lane & 3;
    const int bm = blockIdx.x * EPC;
    const int lr0 = warp * 16 + gid;

    // stage edge_attr fp32 (192 rows x 128 cols)
    for (int i = tid; i < 6144; i += 384) {
        int r = i >> 5, q = i & 31;
        int gr = bm + r;
        uint32_t doff = (uint32_t)(r * SA_ST + q * 4) * 4;
        if (gr < N_EDGES)
            cp16(sb + G1_SA + doff, edge_attr + (size_t)gr * 128 + q * 4);
        else
            *reinterpret_cast<uint4*>(smem + G1_SA + doff) = make_uint4(0u, 0u, 0u, 0u);
    }
    for (int i = tid; i < 4096; i += 384)
        cp16(sb + G1_BPK + (uint32_t)i * 16, g_B1pk + i);
    if (tid < 32) cp16(sb + G1_BIAS + tid * 16, fc1_b + tid * 4);
    CP_COMMIT();
    CP_WAIT0();
    __syncthreads();

    // hoist A fragments with on-the-fly split (proven indexing)
    uint32_t ah[8][4], al[8][4];
    {
        const float* As = reinterpret_cast<const float*>(smem + G1_SA);
        #pragma unroll
        for (int ks = 0; ks < 8; ks++) {
            int c = ks * 16 + qid * 2;
            float2 v00 = *reinterpret_cast<const float2*>(&As[lr0 * SA_ST + c]);
            float2 v10 = *reinterpret_cast<const float2*>(&As[(lr0 + 8) * SA_ST + c]);
            float2 v01 = *reinterpret_cast<const float2*>(&As[lr0 * SA_ST + c + 8]);
            float2 v11 = *reinterpret_cast<const float2*>(&As[(lr0 + 8) * SA_ST + c + 8]);
            split_pair(v00.x, v00.y, ah[ks][0], al[ks][0]);
            split_pair(v10.x, v10.y, ah[ks][1], al[ks][1]);
            split_pair(v01.x, v01.y, ah[ks][2], al[ks][2]);
            split_pair(v11.x, v11.y, ah[ks][3], al[ks][3]);
        }
    }

    const float* b1s = reinterpret_cast<const float*>(smem + G1_BIAS);
    const uint4* bp = reinterpret_cast<const uint4*>(smem + G1_BPK);
    const int gr0 = bm + lr0, gr1 = bm + lr0 + 8;

    for (int q = 0; q < 4; q++) {
        float acc[4][4];
        #pragma unroll
        for (int j = 0; j < 4; j++)
            #pragma unroll
            for (int i = 0; i < 4; i++) acc[j][i] = 0.f;
        const uint4* fp = bp + (4 * q) * 256 + lane;
        #pragma unroll
        for (int ks = 0; ks < 8; ks++) {
            uint4 f[4];
            #pragma unroll
            for (int j = 0; j < 4; j++) f[j] = fp[j * 256 + ks * 32];
            #pragma unroll
            for (int j = 0; j < 4; j++) mma16816(acc[j], ah[ks], f[j].x, f[j].y);
            #pragma unroll
            for (int j = 0; j < 4; j++) mma16816(acc[j], ah[ks], f[j].z, f[j].w);
            #pragma unroll
            for (int j = 0; j < 4; j++) mma16816(acc[j], al[ks], f[j].x, f[j].y);
        }
        // epilogue: bias + relu + split -> guarded stores
        #pragma unroll
        for (int j = 0; j < 4; j++) {
            const int col = (4 * q + j) * 8 + qid * 2;
            const float b0 = b1s[col], b1 = b1s[col + 1];
            uint32_t h, l;
            if (gr0 < N_EDGES) {
                float v0 = fmaxf(acc[j][0] + b0, 0.f);
                float v1 = fmaxf(acc[j][1] + b1, 0.f);
                split_pair(v0, v1, h, l);
                *reinterpret_cast<uint32_t*>(g_Hhi + (size_t)gr0 * 128 + col) = h;
                *reinterpret_cast<uint32_t*>(g_Hlo + (size_t)gr0 * 128 + col) = l;
            }
            if (gr1 < N_EDGES) {
                float v2 = fmaxf(acc[j][2] + b0, 0.f);
                float v3 = fmaxf(acc[j][3] + b1, 0.f);
                split_pair(v2, v3, h, l);
                *reinterpret_cast<uint32_t*>(g_Hhi + (size_t)gr1 * 128 + col) = h;
                *reinterpret_cast<uint32_t*>(g_Hlo + (size_t)gr1 * 128 + col) = l;
            }
        }
    }
}

// ==================================================================
// GEMM2 + TP + scatter: 384 threads (12 warps), 192 edges/CTA,
// quad accumulator chains, cp.async double-buffered B tiles
// ==================================================================
#define SM_B0   0         // 65536: A-hi staging, then even B tiles
#define SM_B1   65536     // 65536: A-lo staging, then odd B tiles
#define A_ST    128
#define SM_X    131072    // 192 * 62 * 4 = 47616
#define X_ST    62
#define SM_BIAS 178688    // 416 uint4 = 6656
#define SMEM_SZ 185344

__global__ void __launch_bounds__(384, 1)
gemm2_tp_kernel(const float* __restrict__ node_attr,
                const int*   __restrict__ edge_index,
                const float* __restrict__ edge_sh,
                const float* __restrict__ fc2_b) {
    extern __shared__ char smem[];
    const uint32_t sb = smem_u32(smem);
    const int tid = threadIdx.x, warp = tid >> 5, lane = tid & 31;
    const int gid = lane >> 2, qid = lane & 3;
    const int bm = blockIdx.x * EPC;
    const int lr0 = warp * 16 + gid;          // 0..191

    // ---- stage A (hi -> B0, lo -> B1), 192 rows x 128 cols bf16 ----
    for (int i = tid; i < 3072; i += 384) {
        int r = i >> 4, q = i & 15;
        int gr = bm + r;
        uint32_t doff = (uint32_t)(r * A_ST + q * 8) * 2;
        if (gr < N_EDGES) {
            cp16(sb + SM_B0 + doff, g_Hhi + (size_t)gr * 128 + q * 8);
            cp16(sb + SM_B1 + doff, g_Hlo + (size_t)gr * 128 + q * 8);
        } else {
            *reinterpret_cast<uint4*>(smem + SM_B0 + doff) = make_uint4(0u, 0u, 0u, 0u);
            *reinterpret_cast<uint4*>(smem + SM_B1 + doff) = make_uint4(0u, 0u, 0u, 0u);
        }
    }
    // ---- bias2 ----
    for (int i = tid; i < 416; i += 384) {
        if (i < 400) cp16(sb + SM_BIAS + i * 16, fc2_b + i * 4);
        else *reinterpret_cast<uint4*>(smem + SM_BIAS + i * 16) = make_uint4(0u, 0u, 0u, 0u);
    }
    // ---- per-edge features ----
    float* xss = reinterpret_cast<float*>(smem + SM_X);
    if (tid < EPC) {
        const int e = bm + tid;
        const bool valid = (e < N_EDGES);
        float* xr = xss + tid * X_ST;
        int dst = valid ? edge_index[N_EDGES + e] : 0;
        for (int j = 0; j < IN_DIM; j++)
            xr[j] = valid ? node_attr[(size_t)dst * IN_DIM + j] : 0.f;
        float y0 = 0.f, yx = 0.f, yy = 0.f, yz = 0.f;
        int srcn = 0;
        if (valid) {
            srcn = edge_index[e];
            y0 = edge_sh[e * 4 + 0]; yx = edge_sh[e * 4 + 1];
            yy = edge_sh[e * 4 + 2]; yz = edge_sh[e * 4 + 3];
        }
        xr[56] = y0; xr[57] = yx; xr[58] = yy; xr[59] = yz;
        reinterpret_cast<int*>(xr)[60] = srcn;
        reinterpret_cast<int*>(xr)[61] = valid ? 1 : 0;
    }
    CP_COMMIT();
    CP_WAIT0();
    __syncthreads();

    // ---- hoist A fragments (proven indexing) ----
    uint32_t afh[8][4], afl[8][4];
    {
        const __nv_bfloat16* Ah = reinterpret_cast<const __nv_bfloat16*>(smem + SM_B0);
        const __nv_bfloat16* Al = reinterpret_cast<const __nv_bfloat16*>(smem + SM_B1);
        #pragma unroll
        for (int ks = 0; ks < 8; ks++) {
            int c = ks * 16 + qid * 2;
            afh[ks][0] = *reinterpret_cast<const uint32_t*>(Ah + lr0 * A_ST + c);
            afh[ks][1] = *reinterpret_cast<const uint32_t*>(Ah + (lr0 + 8) * A_ST + c);
            afh[ks][2] = *reinterpret_cast<const uint32_t*>(Ah + lr0 * A_ST + c + 8);
            afh[ks][3] = *reinterpret_cast<const uint32_t*>(Ah + (lr0 + 8) * A_ST + c + 8);
            afl[ks][0] = *reinterpret_cast<const uint32_t*>(Al + lr0 * A_ST + c);
            afl[ks][1] = *reinterpret_cast<const uint32_t*>(Al + (lr0 + 8) * A_ST + c);
            afl[ks][2] = *reinterpret_cast<const uint32_t*>(Al + lr0 * A_ST + c + 8);
            afl[ks][3] = *reinterpret_cast<const uint32_t*>(Al + (lr0 + 8) * A_ST + c + 8);
        }
    }
    __syncthreads();   // staging regions now reusable as B tile buffers

    // ---- prefetch packed B tiles 0, 1 ----
    auto loadPK = [&](int nt, uint32_t base) {
        const uint4* srcp = g_B2pk + nt * 4096;
        for (int i = tid; i < 4096; i += 384)
            cp16(base + (uint32_t)i * 16, srcp + i);
    };
    loadPK(0, sb + SM_B0); CP_COMMIT();
    loadPK(1, sb + SM_B1); CP_COMMIT();

    // ---- TP accumulators ----
    float out0[16], out1[12], s1a[4];
    #pragma unroll
    for (int i = 0; i < 16; i++) out0[i] = 0.f;
    #pragma unroll
    for (int i = 0; i < 12; i++) out1[i] = 0.f;
    #pragma unroll
    for (int i = 0; i < 4; i++)  s1a[i] = 0.f;

    const float alpha = 0.15811388300841897f;         // 1/sqrt(40)
    const float cBc   = alpha * 0.57735026918962576f; // alpha/sqrt(3)
    const float* xr0 = xss + lr0 * X_ST;
    const float* xr1 = xss + (lr0 + 8) * X_ST;
    const float* b2s = reinterpret_cast<const float*>(smem + SM_BIAS);

    // epilogue for one 8-col block (proven branch structure)
    auto epi = [&](int nt, int n8, const float* a) {
        const int coll = n8 * 8 + qid * 2;
        const float bv0 = b2s[nt * 128 + coll], bv1 = b2s[nt * 128 + coll + 1];
        const int gblk = nt * 16 + n8;
        #pragma unroll
        for (int e = 0; e < 2; e++) {
            const float* xr = e ? xr1 : xr0;
            const float v0 = a[e * 2 + 0] + bv0;
            const float v1 = a[e * 2 + 1] + bv1;
            if (gblk < 128) {                        // w00
                const int u = gblk >> 2;
                const float coeff = xr[u] * (alpha * xr[56]);
                const int o = e * 8 + (n8 & 3) * 2;
                out0[o + 0] = fmaf(coeff, v0, out0[o + 0]);
                out0[o + 1] = fmaf(coeff, v1, out0[o + 1]);
            } else if (gblk < 160) {                 // w11
                const int u = (gblk - 128) >> 2;
                const float du = xr[32 + u * 3 + 0] * xr[57]
                               + xr[32 + u * 3 + 1] * xr[58]
                               + xr[32 + u * 3 + 2] * xr[59];
                const float coeff = du * cBc;
                const int o = e * 8 + (n8 & 3) * 2;
                out0[o + 0] = fmaf(coeff, v0, out0[o + 0]);
                out0[o + 1] = fmaf(coeff, v1, out0[o + 1]);
            } else if (gblk < 192) {                 // w01 -> s1
                const float xu = xr[gblk - 160];
                s1a[e * 2 + 0] = fmaf(xu, v0, s1a[e * 2 + 0]);
                s1a[e * 2 + 1] = fmaf(xu, v1, s1a[e * 2 + 1]);
            } else {                                 // w10 -> out1
                const int u = gblk - 192;
                const float cy0 = alpha * xr[56];
                const float x0 = xr[32 + u * 3 + 0] * cy0;
                const float x1 = xr[32 + u * 3 + 1] * cy0;
                const float x2 = xr[32 + u * 3 + 2] * cy0;
                const int o = e * 6;
                out1[o + 0] = fmaf(x0, v0, out1[o + 0]);
                out1[o + 1] = fmaf(x1, v0, out1[o + 1]);
                out1[o + 2] = fmaf(x2, v0, out1[o + 2]);
                out1[o + 3] = fmaf(x0, v1, out1[o + 3]);
                out1[o + 4] = fmaf(x1, v1, out1[o + 4]);
                out1[o + 5] = fmaf(x2, v1, out1[o + 5]);
            }
        }
    };

    // ---- main loop over 13 N-tiles, quad chains ----
    for (int nt = 0; nt < NT; nt++) {
        CP_WAIT1();
        __syncthreads();
        const uint32_t bufoff = (nt & 1) ? SM_B1 : SM_B0;
        const uint4* bp = reinterpret_cast<const uint4*>(smem + bufoff);
        const int nquad = (nt == 12) ? 2 : 4;       // cols >= 1600 are padding

        for (int q = 0; q < nquad; q++) {
            float acc[4][4];
            #pragma unroll
            for (int j = 0; j < 4; j++)
                #pragma unroll
                for (int i = 0; i < 4; i++) acc[j][i] = 0.f;
            const uint4* fp = bp + (4 * q) * 256 + lane;
            #pragma unroll
            for (int ks = 0; ks < 8; ks++) {
                uint4 f[4];
                #pragma unroll
                for (int j = 0; j < 4; j++) f[j] = fp[j * 256 + ks * 32];
                #pragma unroll
                for (int j = 0; j < 4; j++) mma16816(acc[j], afh[ks], f[j].x, f[j].y);
                #pragma unroll
                for (int j = 0; j < 4; j++) mma16816(acc[j], afh[ks], f[j].z, f[j].w);
                #pragma unroll
                for (int j = 0; j < 4; j++) mma16816(acc[j], afl[ks], f[j].x, f[j].y);
            }
            epi(nt, 4 * q + 0, acc[0]);
            epi(nt, 4 * q + 1, acc[1]);
            epi(nt, 4 * q + 2, acc[2]);
            epi(nt, 4 * q + 3, acc[3]);
        }
        __syncthreads();                 // buffer fully consumed
        if (nt + 2 < NT) loadPK(nt + 2, sb + bufoff);
        CP_COMMIT();                     // commit every iteration
    }

    // ---- fold w01 path, scatter ----
    #pragma unroll
    for (int e = 0; e < 2; e++) {
        const float* xr = e ? xr1 : xr0;
        if (!reinterpret_cast<const int*>(xr)[61]) continue;
        const int srcn = reinterpret_cast<const int*>(xr)[60];
        const float yx = xr[57], yy = xr[58], yz = xr[59];
        #pragma unroll
        for (int p = 0; p < 2; p++) {
            const float sw = s1a[e * 2 + p] * alpha;
            out1[e * 6 + p * 3 + 0] = fmaf(sw, yx, out1[e * 6 + p * 3 + 0]);
            out1[e * 6 + p * 3 + 1] = fmaf(sw, yy, out1[e * 6 + p * 3 + 1]);
            out1[e * 6 + p * 3 + 2] = fmaf(sw, yz, out1[e * 6 + p * 3 + 2]);
        }
        float* dstp = g_num + (size_t)srcn * IN_DIM;
        #pragma unroll
        for (int q = 0; q < 4; q++)
            #pragma unroll
            for (int p = 0; p < 2; p++) {
                const int w = q * 8 + qid * 2 + p;
                atomicAdd(&dstp[w], out0[e * 8 + q * 2 + p]);
            }
        #pragma unroll
        for (int p = 0; p < 2; p++) {
            const int w8 = qid * 2 + p;
            atomicAdd(&dstp[32 + w8 * 3 + 0], out1[e * 6 + p * 3 + 0]);
            atomicAdd(&dstp[32 + w8 * 3 + 1], out1[e * 6 + p * 3 + 1]);
            atomicAdd(&dstp[32 + w8 * 3 + 2], out1[e * 6 + p * 3 + 2]);
        }
        if (qid == 0) atomicAdd(&g_cnt[srcn], 1.0f);
    }
}

// ==================================================================
// finalize 1: out_pre = num/max(cnt,1) + node_attr, accumulate BN stats
// ==================================================================
__global__ void finalize1_kernel(const float* __restrict__ node_attr,
                                 float* __restrict__ staged) {
    __shared__ float s_stats[72];
    const int t = threadIdx.x;
    if (t < 72) s_stats[t] = 0.f;
    __syncthreads();

    const int n = blockIdx.x * blockDim.x + t;
    const bool valid = (n < N_NODES);
    float ic = 0.f;
    if (valid) ic = 1.f / fmaxf(g_cnt[n], 1.f);
    const int lane = t & 31;

    for (int j = 0; j < 32; j++) {
        float o = 0.f;
        if (valid) {
            o = g_num[(size_t)n * IN_DIM + j] * ic + node_attr[(size_t)n * IN_DIM + j];
            staged[(size_t)n * IN_DIM + j] = o;
        }
        float so = o, so2 = o * o;
        #pragma unroll
        for (int off = 16; off > 0; off >>= 1) {
            so  += __shfl_down_sync(0xffffffffu, so,  off);
            so2 += __shfl_down_sync(0xffffffffu, so2, off);
        }
        if (lane == 0) { atomicAdd(&s_stats[j], so); atomicAdd(&s_stats[32 + j], so2); }
    }
    for (int j = 32; j < 56; j++) {
        float o = 0.f;
        if (valid) {
            o = g_num[(size_t)n * IN_DIM + j] * ic + node_attr[(size_t)n * IN_DIM + j];
            staged[(size_t)n * IN_DIM + j] = o;
        }
        float so2 = o * o;
        #pragma unroll
        for (int off = 16; off > 0; off >>= 1)
            so2 += __shfl_down_sync(0xffffffffu, so2, off);
        if (lane == 0) atomicAdd(&s_stats[64 + (j - 32) / 3], so2);
    }
    __syncthreads();
    if (t < 72) atomicAdd(&g_stats[t], s_stats[t]);
}

// ==================================================================
// finalize 2: batch norm in place on d_out
// ==================================================================
__global__ void finalize2_kernel(const float* __restrict__ bn_w_s,
                                 const float* __restrict__ bn_w_v,
                                 const float* __restrict__ bn_b_s,
                                 float* __restrict__ out) {
    const int idx = blockIdx.x * blockDim.x + threadIdx.x;
    if (idx >= N_NODES * IN_DIM) return;
    const int j = idx % IN_DIM;
    const float x = out[idx];
    const float invN = 1.0f / (float)N_NODES;
    if (j < 32) {
        float mean = g_stats[j] * invN;
        float var  = g_stats[32 + j] * invN - mean * mean;
        out[idx] = (x - mean) * rsqrtf(var + 1e-5f) * bn_w_s[j] + bn_b_s[j];
    } else {
        int u = (j - 32) / 3;
        float vn = g_stats[64 + u] * invN * (1.0f / 3.0f);
        out[idx] = x * rsqrtf(vn + 1e-5f) * bn_w_v[u];
    }
}

// ==================================================================
extern "C" void kernel_launch(void* const* d_in, const int* in_sizes, int n_in,
                              void* d_out, int out_size) {
    const float* node_attr  = (const float*)d_in[0];
    const int*   edge_index = (const int*)d_in[1];
    const float* edge_attr  = (const float*)d_in[2];
    const float* edge_sh    = (const float*)d_in[3];
    const float* fc1_w      = (const float*)d_in[4];
    const float* fc1_b      = (const float*)d_in[5];
    const float* fc2_w      = (const float*)d_in[6];
    const float* fc2_b      = (const float*)d_in[7];
    const float* bn_w_s     = (const float*)d_in[8];
    const float* bn_w_v     = (const float*)d_in[9];
    const float* bn_b_s     = (const float*)d_in[10];
    float* out = (float*)d_out;

    cudaFuncSetAttribute(gemm2_tp_kernel,
                         cudaFuncAttributeMaxDynamicSharedMemorySize, SMEM_SZ);
    cudaFuncSetAttribute(sgemm1_mma_kernel,
                         cudaFuncAttributeMaxDynamicSharedMemorySize, G1_SMEM);

    zero_kernel<<<(N_NODES * IN_DIM + N_NODES + 72 + 255) / 256, 256>>>();
    prepB_kernel<false><<<(NT * 4096 + 255) / 256, 256>>>(fc2_w);
    prepB_kernel<true><<<(4096 + 255) / 256, 256>>>(fc1_w);
    sgemm1_mma_kernel<<<M_TILES, 384, G1_SMEM>>>(edge_attr, fc1_b);
    gemm2_tp_kernel<<<M_TILES, 384, SMEM_SZ>>>(node_attr, edge_index, edge_sh, fc2_b);
    finalize1_kernel<<<(N_NODES + 255) / 256, 256>>>(node_attr, out);
    finalize2_kernel<<<(N_NODES * IN_DIM + 255) / 256, 256>>>(bn_w_s, bn_w_v, bn_b_s, out);
}

// round 15
// speedup vs baseline: 1.4501x; 1.4501x over previous
#include <cuda_runtime.h>
#include <cuda_bf16.h>
#include <stdint.h>

#define N_NODES 10000
#define N_EDGES 100000
#define HIDDEN  128
#define WN      1600
#define IN_DIM  56
#define NT      13
#define EPC2    256                            // edges per CTA (gemm2)
#define GRID2   ((N_EDGES + EPC2 - 1) / EPC2)  // 391
#define EPC1    192                            // edges per CTA (gemm1)
#define GRID1   ((N_EDGES + EPC1 - 1) / EPC1)  // 521

// ---- scratch (static __device__; aligned for cp.async 16B) ----
__device__ __align__(256) __nv_bfloat16 g_Hhi[(size_t)N_EDGES * HIDDEN];
__device__ __align__(256) __nv_bfloat16 g_Hlo[(size_t)N_EDGES * HIDDEN];
__device__ __align__(256) uint4 g_B2pk[NT * 4096];   // packed fc2 fragments
__device__ __align__(256) uint4 g_B1pk[4096];        // packed fc1 fragments
__device__ __align__(256) float g_num[(size_t)N_NODES * IN_DIM];
__device__ __align__(256) float g_cnt[N_NODES];
__device__ __align__(256) float g_stats[72];

// ==================================================================
// PTX helpers
// ==================================================================
__device__ __forceinline__ uint32_t smem_u32(const void* p) {
    uint32_t a;
    asm("{ .reg .u64 t; cvta.to.shared.u64 t, %1; cvt.u32.u64 %0, t; }"
        : "=r"(a) : "l"(p));
    return a;
}
__device__ __forceinline__ void mma16816(float* c, const uint32_t* a,
                                         uint32_t b0, uint32_t b1) {
    asm volatile(
        "mma.sync.aligned.m16n8k16.row.col.f32.bf16.bf16.f32 "
        "{%0,%1,%2,%3}, {%4,%5,%6,%7}, {%8,%9}, {%0,%1,%2,%3};"
        : "+f"(c[0]), "+f"(c[1]), "+f"(c[2]), "+f"(c[3])
        : "r"(a[0]), "r"(a[1]), "r"(a[2]), "r"(a[3]), "r"(b0), "r"(b1));
}
__device__ __forceinline__ void cp16(uint32_t dst, const void* src) {
    asm volatile("cp.async.cg.shared.global [%0], [%1], 16;" :: "r"(dst), "l"(src));
}
#define CP_COMMIT() asm volatile("cp.async.commit_group;" ::: "memory")
#define CP_WAIT0()  asm volatile("cp.async.wait_group 0;" ::: "memory")
#define CP_WAIT1()  asm volatile("cp.async.wait_group 1;" ::: "memory")

__device__ __forceinline__ void split_pair(float v0, float v1,
                                           uint32_t& hi, uint32_t& lo) {
    __nv_bfloat16 h0 = __float2bfloat16(v0), h1 = __float2bfloat16(v1);
    hi = (uint32_t)__bfloat16_as_ushort(h0)
       | ((uint32_t)__bfloat16_as_ushort(h1) << 16);
    __nv_bfloat16 l0 = __float2bfloat16(v0 - __bfloat162float(h0));
    __nv_bfloat16 l1 = __float2bfloat16(v1 - __bfloat162float(h1));
    lo = (uint32_t)__bfloat16_as_ushort(l0)
       | ((uint32_t)__bfloat16_as_ushort(l1) << 16);
}

// ==================================================================
// setup: zero accumulators + pack fc1/fc2 fragments (ONE launch)
// pack layout (proven): idx = ((nt*16+n8)*8+ks)*32+lane
//   n = nt*128 + n8*8 + lane/4 ; k = ks*16 + (lane%4)*2
//   uint4 = { hi(k,k+1), hi(k+8,k+9), lo(k,k+1), lo(k+8,k+9) }
// destinations referenced as device symbols IN DEVICE CODE only.
// ==================================================================
__global__ void setup_kernel(const float* __restrict__ fc2_w,
                             const float* __restrict__ fc1_w) {
    int i = blockIdx.x * blockDim.x + threadIdx.x;
    const int z0 = N_NODES * IN_DIM;            // 560000
    const int z1 = z0 + N_NODES;                // 570000
    const int z2 = z1 + 72;                     // 570072
    const int p2 = z2 + NT * 4096;              // + fc2 pack
    const int p1 = p2 + 4096;                   // + fc1 pack
    if (i < z0) { g_num[i] = 0.f; return; }
    if (i < z1) { g_cnt[i - z0] = 0.f; return; }
    if (i < z2) { g_stats[i - z1] = 0.f; return; }
    if (i >= p1) return;

    const bool isB1 = (i >= p2);
    const int idx = isB1 ? (i - p2) : (i - z2);
    const float* src = isB1 ? fc1_w : fc2_w;
    const int nvalid = isB1 ? 128 : WN;
    const int ld     = isB1 ? 128 : WN;
    uint4* dst = isB1 ? g_B1pk : g_B2pk;

    int lane = idx & 31;
    int ks   = (idx >> 5) & 7;
    int n8   = (idx >> 8) & 15;
    int nt   = idx >> 12;
    int n = nt * 128 + n8 * 8 + (lane >> 2);
    int k = ks * 16 + (lane & 3) * 2;
    float v0 = 0.f, v1 = 0.f, v2 = 0.f, v3 = 0.f;
    if (n < nvalid) {
        v0 = src[(size_t)k * ld + n];
        v1 = src[(size_t)(k + 1) * ld + n];
        v2 = src[(size_t)(k + 8) * ld + n];
        v3 = src[(size_t)(k + 9) * ld + n];
    }
    uint32_t h01, l01, h23, l23;
    split_pair(v0, v1, h01, l01);
    split_pair(v2, v3, h23, l23);
    dst[idx] = make_uint4(h01, h23, l01, l23);
}
#define SETUP_TOTAL (N_NODES * IN_DIM + N_NODES + 72 + NT * 4096 + 4096)

// ==================================================================
// GEMM1 (HMMA split-bf16): H = relu(edge_attr@fc1+b1) -> g_Hhi/g_Hlo
// 384 threads, 192 edges/CTA, quad accumulator chains (PROVEN R13, 79us)
// ==================================================================
#define SA_ST   132
#define G1_SA   0                       // 192*132*4 = 101376
#define G1_BPK  101376                  // 65536
#define G1_BIAS 166912                  // 512
#define G1_SMEM 167424

__global__ void __launch_bounds__(384, 1)
sgemm1_mma_kernel(const float* __restrict__ edge_attr,
                  const float* __restrict__ fc1_b) {
    extern __shared__ char smem[];
    const uint32_t sb = smem_u32(smem);
    const int tid = threadIdx.x, warp = tid >> 5, lane = tid & 31;
    const int gid = lane >> 2, qid = lane & 3;
    const int bm = blockIdx.x * EPC1;
    const int lr0 = warp * 16 + gid;

    // stage edge_attr fp32 (192 rows x 128 cols)
    for (int i = tid; i < 6144; i += 384) {
        int r = i >> 5, q = i & 31;
        int gr = bm + r;
        uint32_t doff = (uint32_t)(r * SA_ST + q * 4) * 4;
        if (gr < N_EDGES)
            cp16(sb + G1_SA + doff, edge_attr + (size_t)gr * 128 + q * 4);
        else
            *reinterpret_cast<uint4*>(smem + G1_SA + doff) = make_uint4(0u, 0u, 0u, 0u);
    }
    for (int i = tid; i < 4096; i += 384)
        cp16(sb + G1_BPK + (uint32_t)i * 16, g_B1pk + i);
    if (tid < 32) cp16(sb + G1_BIAS + tid * 16, fc1_b + tid * 4);
    CP_COMMIT();
    CP_WAIT0();
    __syncthreads();

    // hoist A fragments with on-the-fly split (proven indexing)
    uint32_t ah[8][4], al[8][4];
    {
        const float* As = reinterpret_cast<const float*>(smem + G1_SA);
        #pragma unroll
        for (int ks = 0; ks < 8; ks++) {
            int c = ks * 16 + qid * 2;
            float2 v00 = *reinterpret_cast<const float2*>(&As[lr0 * SA_ST + c]);
            float2 v10 = *reinterpret_cast<const float2*>(&As[(lr0 + 8) * SA_ST + c]);
            float2 v01 = *reinterpret_cast<const float2*>(&As[lr0 * SA_ST + c + 8]);
            float2 v11 = *reinterpret_cast<const float2*>(&As[(lr0 + 8) * SA_ST + c + 8]);
            split_pair(v00.x, v00.y, ah[ks][0], al[ks][0]);
            split_pair(v10.x, v10.y, ah[ks][1], al[ks][1]);
            split_pair(v01.x, v01.y, ah[ks][2], al[ks][2]);
            split_pair(v11.x, v11.y, ah[ks][3], al[ks][3]);
        }
    }

    const float* b1s = reinterpret_cast<const float*>(smem + G1_BIAS);
    const uint4* bp = reinterpret_cast<const uint4*>(smem + G1_BPK);
    const int gr0 = bm + lr0, gr1 = bm + lr0 + 8;

    for (int q = 0; q < 4; q++) {
        float acc[4][4];
        #pragma unroll
        for (int j = 0; j < 4; j++)
            #pragma unroll
            for (int i = 0; i < 4; i++) acc[j][i] = 0.f;
        const uint4* fp = bp + (4 * q) * 256 + lane;
        #pragma unroll
        for (int ks = 0; ks < 8; ks++) {
            uint4 f[4];
            #pragma unroll
            for (int j = 0; j < 4; j++) f[j] = fp[j * 256 + ks * 32];
            #pragma unroll
            for (int j = 0; j < 4; j++) mma16816(acc[j], ah[ks], f[j].x, f[j].y);
            #pragma unroll
            for (int j = 0; j < 4; j++) mma16816(acc[j], ah[ks], f[j].z, f[j].w);
            #pragma unroll
            for (int j = 0; j < 4; j++) mma16816(acc[j], al[ks], f[j].x, f[j].y);
        }
        // epilogue: bias + relu + split -> guarded stores
        #pragma unroll
        for (int j = 0; j < 4; j++) {
            const int col = (4 * q + j) * 8 + qid * 2;
            const float b0 = b1s[col], b1 = b1s[col + 1];
            uint32_t h, l;
            if (gr0 < N_EDGES) {
                float v0 = fmaxf(acc[j][0] + b0, 0.f);
                float v1 = fmaxf(acc[j][1] + b1, 0.f);
                split_pair(v0, v1, h, l);
                *reinterpret_cast<uint32_t*>(g_Hhi + (size_t)gr0 * 128 + col) = h;
                *reinterpret_cast<uint32_t*>(g_Hlo + (size_t)gr0 * 128 + col) = l;
            }
            if (gr1 < N_EDGES) {
                float v2 = fmaxf(acc[j][2] + b0, 0.f);
                float v3 = fmaxf(acc[j][3] + b1, 0.f);
                split_pair(v2, v3, h, l);
                *reinterpret_cast<uint32_t*>(g_Hhi + (size_t)gr1 * 128 + col) = h;
                *reinterpret_cast<uint32_t*>(g_Hlo + (size_t)gr1 * 128 + col) = l;
            }
        }
    }
}

// ==================================================================
// GEMM2 + TP + scatter: 1 CTA = 256 edges, 512 threads (16 warps)
// dual accumulator chains, cp.async double-buffered B tiles
// (PROVEN R11 version, 382us)
// ==================================================================
#define SM_B0   0         // 65536: A-hi staging, then even B tiles
#define SM_B1   65536     // 65536: A-lo staging, then odd B tiles
#define A_ST    128
#define SM_X    131072    // 256 * 62 * 4 = 63488
#define X_ST    62
#define SM_BIAS 194560    // 416 uint4 = 6656
#define SMEM_SZ 201216

__global__ void __launch_bounds__(512, 1)
gemm2_tp_kernel(const float* __restrict__ node_attr,
                const int*   __restrict__ edge_index,
                const float* __restrict__ edge_sh,
                const float* __restrict__ fc2_b) {
    extern __shared__ char smem[];
    const uint32_t sb = smem_u32(smem);
    const int tid = threadIdx.x, warp = tid >> 5, lane = tid & 31;
    const int gid = lane >> 2, qid = lane & 3;
    const int bm = blockIdx.x * EPC2;
    const int lr0 = warp * 16 + gid;          // 0..255

    // ---- stage A (hi -> B0, lo -> B1), 256 rows x 128 cols bf16 ----
    for (int i = tid; i < 4096; i += 512) {
        int r = i >> 4, q = i & 15;
        int gr = bm + r;
        uint32_t doff = (uint32_t)(r * A_ST + q * 8) * 2;
        if (gr < N_EDGES) {
            cp16(sb + SM_B0 + doff, g_Hhi + (size_t)gr * 128 + q * 8);
            cp16(sb + SM_B1 + doff, g_Hlo + (size_t)gr * 128 + q * 8);
        } else {
            *reinterpret_cast<uint4*>(smem + SM_B0 + doff) = make_uint4(0u, 0u, 0u, 0u);
            *reinterpret_cast<uint4*>(smem + SM_B1 + doff) = make_uint4(0u, 0u, 0u, 0u);
        }
    }
    // ---- bias2 ----
    for (int i = tid; i < 416; i += 512) {
        if (i < 400) cp16(sb + SM_BIAS + i * 16, fc2_b + i * 4);
        else *reinterpret_cast<uint4*>(smem + SM_BIAS + i * 16) = make_uint4(0u, 0u, 0u, 0u);
    }
    // ---- per-edge features ----
    float* xss = reinterpret_cast<float*>(smem + SM_X);
    if (tid < EPC2) {
        const int e = bm + tid;
        const bool valid = (e < N_EDGES);
        float* xr = xss + tid * X_ST;
        int dst = valid ? edge_index[N_EDGES + e] : 0;
        for (int j = 0; j < IN_DIM; j++)
            xr[j] = valid ? node_attr[(size_t)dst * IN_DIM + j] : 0.f;
        float y0 = 0.f, yx = 0.f, yy = 0.f, yz = 0.f;
        int srcn = 0;
        if (valid) {
            srcn = edge_index[e];
            y0 = edge_sh[e * 4 + 0]; yx = edge_sh[e * 4 + 1];
            yy = edge_sh[e * 4 + 2]; yz = edge_sh[e * 4 + 3];
        }
        xr[56] = y0; xr[57] = yx; xr[58] = yy; xr[59] = yz;
        reinterpret_cast<int*>(xr)[60] = srcn;
        reinterpret_cast<int*>(xr)[61] = valid ? 1 : 0;
    }
    CP_COMMIT();
    CP_WAIT0();
    __syncthreads();

    // ---- hoist A fragments (proven indexing; one-time LDS) ----
    uint32_t afh[8][4], afl[8][4];
    {
        const __nv_bfloat16* Ah = reinterpret_cast<const __nv_bfloat16*>(smem + SM_B0);
        const __nv_bfloat16* Al = reinterpret_cast<const __nv_bfloat16*>(smem + SM_B1);
        #pragma unroll
        for (int ks = 0; ks < 8; ks++) {
            int c = ks * 16 + qid * 2;
            afh[ks][0] = *reinterpret_cast<const uint32_t*>(Ah + lr0 * A_ST + c);
            afh[ks][1] = *reinterpret_cast<const uint32_t*>(Ah + (lr0 + 8) * A_ST + c);
            afh[ks][2] = *reinterpret_cast<const uint32_t*>(Ah + lr0 * A_ST + c + 8);
            afh[ks][3] = *reinterpret_cast<const uint32_t*>(Ah + (lr0 + 8) * A_ST + c + 8);
            afl[ks][0] = *reinterpret_cast<const uint32_t*>(Al + lr0 * A_ST + c);
            afl[ks][1] = *reinterpret_cast<const uint32_t*>(Al + (lr0 + 8) * A_ST + c);
            afl[ks][2] = *reinterpret_cast<const uint32_t*>(Al + lr0 * A_ST + c + 8);
            afl[ks][3] = *reinterpret_cast<const uint32_t*>(Al + (lr0 + 8) * A_ST + c + 8);
        }
    }
    __syncthreads();   // staging regions now reusable as B tile buffers

    // ---- prefetch packed B tiles 0, 1 ----
    auto loadPK = [&](int nt, uint32_t base) {
        const uint4* srcp = g_B2pk + nt * 4096;
        for (int i = tid; i < 4096; i += 512)
            cp16(base + (uint32_t)i * 16, srcp + i);
    };
    loadPK(0, sb + SM_B0); CP_COMMIT();
    loadPK(1, sb + SM_B1); CP_COMMIT();

    // ---- TP accumulators ----
    float out0[16], out1[12], s1a[4];
    #pragma unroll
    for (int i = 0; i < 16; i++) out0[i] = 0.f;
    #pragma unroll
    for (int i = 0; i < 12; i++) out1[i] = 0.f;
    #pragma unroll
    for (int i = 0; i < 4; i++)  s1a[i] = 0.f;

    const float alpha = 0.15811388300841897f;         // 1/sqrt(40)
    const float cBc   = alpha * 0.57735026918962576f; // alpha/sqrt(3)
    const float* xr0 = xss + lr0 * X_ST;
    const float* xr1 = xss + (lr0 + 8) * X_ST;
    const float* b2s = reinterpret_cast<const float*>(smem + SM_BIAS);

    // epilogue for one 8-col tile (proven branch structure)
    auto epi = [&](int nt, int n8, const float* a) {
        const int coll = n8 * 8 + qid * 2;
        const float bv0 = b2s[nt * 128 + coll], bv1 = b2s[nt * 128 + coll + 1];
        const int gblk = nt * 16 + n8;
        #pragma unroll
        for (int e = 0; e < 2; e++) {
            const float* xr = e ? xr1 : xr0;
            const float v0 = a[e * 2 + 0] + bv0;
            const float v1 = a[e * 2 + 1] + bv1;
            if (gblk < 128) {                        // w00
                const int u = gblk >> 2;
                const float coeff = xr[u] * (alpha * xr[56]);
                const int o = e * 8 + (n8 & 3) * 2;
                out0[o + 0] = fmaf(coeff, v0, out0[o + 0]);
                out0[o + 1] = fmaf(coeff, v1, out0[o + 1]);
            } else if (gblk < 160) {                 // w11
                const int u = (gblk - 128) >> 2;
                const float du = xr[32 + u * 3 + 0] * xr[57]
                               + xr[32 + u * 3 + 1] * xr[58]
                               + xr[32 + u * 3 + 2] * xr[59];
                const float coeff = du * cBc;
                const int o = e * 8 + (n8 & 3) * 2;
                out0[o + 0] = fmaf(coeff, v0, out0[o + 0]);
                out0[o + 1] = fmaf(coeff, v1, out0[o + 1]);
            } else if (gblk < 192) {                 // w01 -> s1
                const float xu = xr[gblk - 160];
                s1a[e * 2 + 0] = fmaf(xu, v0, s1a[e * 2 + 0]);
                s1a[e * 2 + 1] = fmaf(xu, v1, s1a[e * 2 + 1]);
            } else {                                 // w10 -> out1
                const int u = gblk - 192;
                const float cy0 = alpha * xr[56];
                const float x0 = xr[32 + u * 3 + 0] * cy0;
                const float x1 = xr[32 + u * 3 + 1] * cy0;
                const float x2 = xr[32 + u * 3 + 2] * cy0;
                const int o = e * 6;
                out1[o + 0] = fmaf(x0, v0, out1[o + 0]);
                out1[o + 1] = fmaf(x1, v0, out1[o + 1]);
                out1[o + 2] = fmaf(x2, v0, out1[o + 2]);
                out1[o + 3] = fmaf(x0, v1, out1[o + 3]);
                out1[o + 4] = fmaf(x1, v1, out1[o + 4]);
                out1[o + 5] = fmaf(x2, v1, out1[o + 5]);
            }
        }
    };

    // ---- main loop over 13 N-tiles ----
    for (int nt = 0; nt < NT; nt++) {
        CP_WAIT1();
        __syncthreads();
        const uint32_t bufoff = (nt & 1) ? SM_B1 : SM_B0;
        const uint4* bp = reinterpret_cast<const uint4*>(smem + bufoff);
        const int npair = (nt == 12) ? 4 : 8;       // cols >= 1600 are padding

        for (int p = 0; p < npair; p++) {
            float a0[4] = {0.f, 0.f, 0.f, 0.f};
            float a1[4] = {0.f, 0.f, 0.f, 0.f};
            const uint4* f0p = bp + (2 * p) * 256 + lane;       // (n8*8+ks)*32+lane
            const uint4* f1p = bp + (2 * p + 1) * 256 + lane;
            #pragma unroll
            for (int ks = 0; ks < 8; ks++) {
                const uint4 f0 = f0p[ks * 32];
                const uint4 f1 = f1p[ks * 32];
                mma16816(a0, afh[ks], f0.x, f0.y);
                mma16816(a1, afh[ks], f1.x, f1.y);
                mma16816(a0, afh[ks], f0.z, f0.w);
                mma16816(a1, afh[ks], f1.z, f1.w);
                mma16816(a0, afl[ks], f0.x, f0.y);
                mma16816(a1, afl[ks], f1.x, f1.y);
            }
            epi(nt, 2 * p,     a0);
            epi(nt, 2 * p + 1, a1);
        }
        __syncthreads();                 // buffer fully consumed
        if (nt + 2 < NT) loadPK(nt + 2, sb + bufoff);
        CP_COMMIT();                     // commit every iteration
    }

    // ---- fold w01 path, scatter ----
    #pragma unroll
    for (int e = 0; e < 2; e++) {
        const float* xr = e ? xr1 : xr0;
        if (!reinterpret_cast<const int*>(xr)[61]) continue;
        const int srcn = reinterpret_cast<const int*>(xr)[60];
        const float yx = xr[57], yy = xr[58], yz = xr[59];
        #pragma unroll
        for (int p = 0; p < 2; p++) {
            const float sw = s1a[e * 2 + p] * alpha;
            out1[e * 6 + p * 3 + 0] = fmaf(sw, yx, out1[e * 6 + p * 3 + 0]);
            out1[e * 6 + p * 3 + 1] = fmaf(sw, yy, out1[e * 6 + p * 3 + 1]);
            out1[e * 6 + p * 3 + 2] = fmaf(sw, yz, out1[e * 6 + p * 3 + 2]);
        }
        float* dstp = g_num + (size_t)srcn * IN_DIM;
        #pragma unroll
        for (int q = 0; q < 4; q++)
            #pragma unroll
            for (int p = 0; p < 2; p++) {
                const int w = q * 8 + qid * 2 + p;
                atomicAdd(&dstp[w], out0[e * 8 + q * 2 + p]);
            }
        #pragma unroll
        for (int p = 0; p < 2; p++) {
            const int w8 = qid * 2 + p;
            atomicAdd(&dstp[32 + w8 * 3 + 0], out1[e * 6 + p * 3 + 0]);
            atomicAdd(&dstp[32 + w8 * 3 + 1], out1[e * 6 + p * 3 + 1]);
            atomicAdd(&dstp[32 + w8 * 3 + 2], out1[e * 6 + p * 3 + 2]);
        }
        if (qid == 0) atomicAdd(&g_cnt[srcn], 1.0f);
    }
}

// ==================================================================
// finalize 1: out_pre = num/max(cnt,1) + node_attr, accumulate BN stats
// ==================================================================
__global__ void finalize1_kernel(const float* __restrict__ node_attr,
                                 float* __restrict__ staged) {
    __shared__ float s_stats[72];
    const int t = threadIdx.x;
    if (t < 72) s_stats[t] = 0.f;
    __syncthreads();

    const int n = blockIdx.x * blockDim.x + t;
    const bool valid = (n < N_NODES);
    float ic = 0.f;
    if (valid) ic = 1.f / fmaxf(g_cnt[n], 1.f);
    const int lane = t & 31;

    for (int j = 0; j < 32; j++) {
        float o = 0.f;
        if (valid) {
            o = g_num[(size_t)n * IN_DIM + j] * ic + node_attr[(size_t)n * IN_DIM + j];
            staged[(size_t)n * IN_DIM + j] = o;
        }
        float so = o, so2 = o * o;
        #pragma unroll
        for (int off = 16; off > 0; off >>= 1) {
            so  += __shfl_down_sync(0xffffffffu, so,  off);
            so2 += __shfl_down_sync(0xffffffffu, so2, off);
        }
        if (lane == 0) { atomicAdd(&s_stats[j], so); atomicAdd(&s_stats[32 + j], so2); }
    }
    for (int j = 32; j < 56; j++) {
        float o = 0.f;
        if (valid) {
            o = g_num[(size_t)n * IN_DIM + j] * ic + node_attr[(size_t)n * IN_DIM + j];
            staged[(size_t)n * IN_DIM + j] = o;
        }
        float so2 = o * o;
        #pragma unroll
        for (int off = 16; off > 0; off >>= 1)
            so2 += __shfl_down_sync(0xffffffffu, so2, off);
        if (lane == 0) atomicAdd(&s_stats[64 + (j - 32) / 3], so2);
    }
    __syncthreads();
    if (t < 72) atomicAdd(&g_stats[t], s_stats[t]);
}

// ==================================================================
// finalize 2: batch norm in place on d_out
// ==================================================================
__global__ void finalize2_kernel(const float* __restrict__ bn_w_s,
                                 const float* __restrict__ bn_w_v,
                                 const float* __restrict__ bn_b_s,
                                 float* __restrict__ out) {
    const int idx = blockIdx.x * blockDim.x + threadIdx.x;
    if (idx >= N_NODES * IN_DIM) return;
    const int j = idx % IN_DIM;
    const float x = out[idx];
    const float invN = 1.0f / (float)N_NODES;
    if (j < 32) {
        float mean = g_stats[j] * invN;
        float var  = g_stats[32 + j] * invN - mean * mean;
        out[idx] = (x - mean) * rsqrtf(var + 1e-5f) * bn_w_s[j] + bn_b_s[j];
    } else {
        int u = (j - 32) / 3;
        float vn = g_stats[64 + u] * invN * (1.0f / 3.0f);
        out[idx] = x * rsqrtf(vn + 1e-5f) * bn_w_v[u];
    }
}

// ==================================================================
extern "C" void kernel_launch(void* const* d_in, const int* in_sizes, int n_in,
                              void* d_out, int out_size) {
    const float* node_attr  = (const float*)d_in[0];
    const int*   edge_index = (const int*)d_in[1];
    const float* edge_attr  = (const float*)d_in[2];
    const float* edge_sh    = (const float*)d_in[3];
    const float* fc1_w      = (const float*)d_in[4];
    const float* fc1_b      = (const float*)d_in[5];
    const float* fc2_w      = (const float*)d_in[6];
    const float* fc2_b      = (const float*)d_in[7];
    const float* bn_w_s     = (const float*)d_in[8];
    const float* bn_w_v     = (const float*)d_in[9];
    const float* bn_b_s     = (const float*)d_in[10];
    float* out = (float*)d_out;

    cudaFuncSetAttribute(gemm2_tp_kernel,
                         cudaFuncAttributeMaxDynamicSharedMemorySize, SMEM_SZ);
    cudaFuncSetAttribute(sgemm1_mma_kernel,
                         cudaFuncAttributeMaxDynamicSharedMemorySize, G1_SMEM);

    setup_kernel<<<(SETUP_TOTAL + 255) / 256, 256>>>(fc2_w, fc1_w);
    sgemm1_mma_kernel<<<GRID1, 384, G1_SMEM>>>(edge_attr, fc1_b);
    gemm2_tp_kernel<<<GRID2, 512, SMEM_SZ>>>(node_attr, edge_index, edge_sh, fc2_b);
    finalize1_kernel<<<(N_NODES + 255) / 256, 256>>>(node_attr, out);
    finalize2_kernel<<<(N_NODES * IN_DIM + 255) / 256, 256>>>(bn_w_s, bn_w_v, bn_b_s, out);
}

// round 16
// speedup vs baseline: 1.5401x; 1.0621x over previous
#include <cuda_runtime.h>
#include <cuda_bf16.h>
#include <stdint.h>

#define N_NODES 10000
#define N_EDGES 100000
#define HIDDEN  128
#define WN      1600
#define IN_DIM  56
#define NT      13
#define EPC2    256                            // edges per CTA
#define GRID2   ((N_EDGES + EPC2 - 1) / EPC2)  // 391

// ---- scratch (static __device__; aligned for cp.async 16B) ----
__device__ __align__(256) uint4 g_B2pk[NT * 4096];   // packed fc2 fragments
__device__ __align__(256) uint4 g_B1pk[4096];        // packed fc1 fragments
__device__ __align__(256) float g_num[(size_t)N_NODES * IN_DIM];
__device__ __align__(256) float g_cnt[N_NODES];
__device__ __align__(256) float g_stats[72];

// ==================================================================
// PTX helpers
// ==================================================================
__device__ __forceinline__ uint32_t smem_u32(const void* p) {
    uint32_t a;
    asm("{ .reg .u64 t; cvta.to.shared.u64 t, %1; cvt.u32.u64 %0, t; }"
        : "=r"(a) : "l"(p));
    return a;
}
__device__ __forceinline__ void mma16816(float* c, const uint32_t* a,
                                         uint32_t b0, uint32_t b1) {
    asm volatile(
        "mma.sync.aligned.m16n8k16.row.col.f32.bf16.bf16.f32 "
        "{%0,%1,%2,%3}, {%4,%5,%6,%7}, {%8,%9}, {%0,%1,%2,%3};"
        : "+f"(c[0]), "+f"(c[1]), "+f"(c[2]), "+f"(c[3])
        : "r"(a[0]), "r"(a[1]), "r"(a[2]), "r"(a[3]), "r"(b0), "r"(b1));
}
__device__ __forceinline__ void cp16(uint32_t dst, const void* src) {
    asm volatile("cp.async.cg.shared.global [%0], [%1], 16;" :: "r"(dst), "l"(src));
}
#define CP_COMMIT() asm volatile("cp.async.commit_group;" ::: "memory")
#define CP_WAIT0()  asm volatile("cp.async.wait_group 0;" ::: "memory")
#define CP_WAIT1()  asm volatile("cp.async.wait_group 1;" ::: "memory")

__device__ __forceinline__ void split_pair(float v0, float v1,
                                           uint32_t& hi, uint32_t& lo) {
    __nv_bfloat16 h0 = __float2bfloat16(v0), h1 = __float2bfloat16(v1);
    hi = (uint32_t)__bfloat16_as_ushort(h0)
       | ((uint32_t)__bfloat16_as_ushort(h1) << 16);
    __nv_bfloat16 l0 = __float2bfloat16(v0 - __bfloat162float(h0));
    __nv_bfloat16 l1 = __float2bfloat16(v1 - __bfloat162float(h1));
    lo = (uint32_t)__bfloat16_as_ushort(l0)
       | ((uint32_t)__bfloat16_as_ushort(l1) << 16);
}

// ==================================================================
// setup: zero accumulators + pack fc1/fc2 fragments (ONE launch)
// destinations referenced as device symbols IN DEVICE CODE only.
// ==================================================================
__global__ void setup_kernel(const float* __restrict__ fc2_w,
                             const float* __restrict__ fc1_w) {
    int i = blockIdx.x * blockDim.x + threadIdx.x;
    const int z0 = N_NODES * IN_DIM;
    const int z1 = z0 + N_NODES;
    const int z2 = z1 + 72;
    const int p2 = z2 + NT * 4096;
    const int p1 = p2 + 4096;
    if (i < z0) { g_num[i] = 0.f; return; }
    if (i < z1) { g_cnt[i - z0] = 0.f; return; }
    if (i < z2) { g_stats[i - z1] = 0.f; return; }
    if (i >= p1) return;

    const bool isB1 = (i >= p2);
    const int idx = isB1 ? (i - p2) : (i - z2);
    const float* src = isB1 ? fc1_w : fc2_w;
    const int nvalid = isB1 ? 128 : WN;
    const int ld     = isB1 ? 128 : WN;
    uint4* dst = isB1 ? g_B1pk : g_B2pk;

    int lane = idx & 31;
    int ks   = (idx >> 5) & 7;
    int n8   = (idx >> 8) & 15;
    int nt   = idx >> 12;
    int n = nt * 128 + n8 * 8 + (lane >> 2);
    int k = ks * 16 + (lane & 3) * 2;
    float v0 = 0.f, v1 = 0.f, v2 = 0.f, v3 = 0.f;
    if (n < nvalid) {
        v0 = src[(size_t)k * ld + n];
        v1 = src[(size_t)(k + 1) * ld + n];
        v2 = src[(size_t)(k + 8) * ld + n];
        v3 = src[(size_t)(k + 9) * ld + n];
    }
    uint32_t h01, l01, h23, l23;
    split_pair(v0, v1, h01, l01);
    split_pair(v2, v3, h23, l23);
    dst[idx] = make_uint4(h01, h23, l01, l23);
}
#define SETUP_TOTAL (N_NODES * IN_DIM + N_NODES + 72 + NT * 4096 + 4096)

// ==================================================================
// FUSED: H = relu(edge_attr@fc1+b1) in regs -> W = H@fc2+b2 -> TP -> scatter
// 512 threads (16 warps), 256 edges/CTA.
// Phase 1: edge_attr fp32 staged in B0/B1; fc1 fragments via LDG (L2-hot);
//          Hacc -> bias/relu/split -> afh/afl registers.
// Phase 2: proven R11 main loop (dual chains, cp.async double buffer).
// ==================================================================
#define SM_B0    0         // 65536
#define SM_B1    65536     // 65536
#define SM_X     131072    // 256 * 62 * 4 = 63488
#define X_ST     62
#define SM_BIAS  194560    // fc2_b: 416 uint4 = 6656
#define SM_BIAS1 201216    // fc1_b: 512
#define SMEM_SZ  201728

__global__ void __launch_bounds__(512, 1)
fused_kernel(const float* __restrict__ node_attr,
             const int*   __restrict__ edge_index,
             const float* __restrict__ edge_sh,
             const float* __restrict__ edge_attr,
             const float* __restrict__ fc1_b,
             const float* __restrict__ fc2_b) {
    extern __shared__ char smem[];
    const uint32_t sb = smem_u32(smem);
    const int tid = threadIdx.x, warp = tid >> 5, lane = tid & 31;
    const int gid = lane >> 2, qid = lane & 3;
    const int bm = blockIdx.x * EPC2;
    const int lr0 = warp * 16 + gid;          // 0..255

    // ---- stage edge_attr fp32: rows 0..127 -> B0, 128..255 -> B1 ----
    for (int i = tid; i < 8192; i += 512) {
        int r = i >> 5, q = i & 31;
        int gr = bm + r;
        uint32_t doff = (r < 128 ? SM_B0 + r * 512 : SM_B1 + (r - 128) * 512)
                      + (uint32_t)q * 16;
        if (gr < N_EDGES)
            cp16(sb + doff, edge_attr + (size_t)gr * 128 + q * 4);
        else
            *reinterpret_cast<uint4*>(smem + doff) = make_uint4(0u, 0u, 0u, 0u);
    }
    // ---- biases ----
    for (int i = tid; i < 416; i += 512) {
        if (i < 400) cp16(sb + SM_BIAS + i * 16, fc2_b + i * 4);
        else *reinterpret_cast<uint4*>(smem + SM_BIAS + i * 16) = make_uint4(0u, 0u, 0u, 0u);
    }
    if (tid < 32) cp16(sb + SM_BIAS1 + tid * 16, fc1_b + tid * 4);
    // ---- per-edge features ----
    float* xss = reinterpret_cast<float*>(smem + SM_X);
    if (tid < EPC2) {
        const int e = bm + tid;
        const bool valid = (e < N_EDGES);
        float* xr = xss + tid * X_ST;
        int dst = valid ? edge_index[N_EDGES + e] : 0;
        for (int j = 0; j < IN_DIM; j++)
            xr[j] = valid ? node_attr[(size_t)dst * IN_DIM + j] : 0.f;
        float y0 = 0.f, yx = 0.f, yy = 0.f, yz = 0.f;
        int srcn = 0;
        if (valid) {
            srcn = edge_index[e];
            y0 = edge_sh[e * 4 + 0]; yx = edge_sh[e * 4 + 1];
            yy = edge_sh[e * 4 + 2]; yz = edge_sh[e * 4 + 3];
        }
        xr[56] = y0; xr[57] = yx; xr[58] = yy; xr[59] = yz;
        reinterpret_cast<int*>(xr)[60] = srcn;
        reinterpret_cast<int*>(xr)[61] = valid ? 1 : 0;
    }
    CP_COMMIT();
    CP_WAIT0();
    __syncthreads();

    // ---- GEMM1: Hacc = edge_attr @ fc1 (split-bf16, 3-term) ----
    float Hacc[16][4];
    #pragma unroll
    for (int i = 0; i < 16; i++)
        #pragma unroll
        for (int j = 0; j < 4; j++) Hacc[i][j] = 0.f;
    {
        const float* Arow0 = reinterpret_cast<const float*>(
            smem + (lr0 < 128 ? SM_B0 + lr0 * 512 : SM_B1 + (lr0 - 128) * 512));
        const float* Arow1 = Arow0 + 8 * 128;   // row lr0+8, same buffer
        for (int ks = 0; ks < 8; ks++) {        // not unrolled: bound regs
            int c = ks * 16 + qid * 2;
            float2 v00 = *reinterpret_cast<const float2*>(Arow0 + c);
            float2 v10 = *reinterpret_cast<const float2*>(Arow1 + c);
            float2 v01 = *reinterpret_cast<const float2*>(Arow0 + c + 8);
            float2 v11 = *reinterpret_cast<const float2*>(Arow1 + c + 8);
            uint32_t ah[4], al[4];
            split_pair(v00.x, v00.y, ah[0], al[0]);
            split_pair(v10.x, v10.y, ah[1], al[1]);
            split_pair(v01.x, v01.y, ah[2], al[2]);
            split_pair(v11.x, v11.y, ah[3], al[3]);
            const uint4* fp = g_B1pk + ks * 32 + lane;
            #pragma unroll
            for (int n8 = 0; n8 < 16; n8++) {
                const uint4 f = fp[n8 * 256];     // (n8*8+ks)*32+lane
                mma16816(Hacc[n8], ah, f.x, f.y);
                mma16816(Hacc[n8], ah, f.z, f.w);
                mma16816(Hacc[n8], al, f.x, f.y);
            }
        }
    }
    // ---- H epilogue: bias + relu + split -> GEMM2 A fragments ----
    uint32_t afh[8][4], afl[8][4];
    {
        const float* b1s = reinterpret_cast<const float*>(smem + SM_BIAS1);
        #pragma unroll
        for (int n8 = 0; n8 < 16; n8++) {
            int col = n8 * 8 + qid * 2;
            float b0 = b1s[col], b1v = b1s[col + 1];
            float v0 = fmaxf(Hacc[n8][0] + b0, 0.f);
            float v1 = fmaxf(Hacc[n8][1] + b1v, 0.f);
            float v2 = fmaxf(Hacc[n8][2] + b0, 0.f);
            float v3 = fmaxf(Hacc[n8][3] + b1v, 0.f);
            int ks2 = n8 >> 1, idx = (n8 & 1) * 2;
            split_pair(v0, v1, afh[ks2][idx],     afl[ks2][idx]);
            split_pair(v2, v3, afh[ks2][idx + 1], afl[ks2][idx + 1]);
        }
    }
    __syncthreads();   // edge_attr staging fully consumed; buffers free

    // ---- prefetch packed B2 tiles 0, 1 ----
    auto loadPK = [&](int nt, uint32_t base) {
        const uint4* srcp = g_B2pk + nt * 4096;
        for (int i = tid; i < 4096; i += 512)
            cp16(base + (uint32_t)i * 16, srcp + i);
    };
    loadPK(0, sb + SM_B0); CP_COMMIT();
    loadPK(1, sb + SM_B1); CP_COMMIT();

    // ---- TP accumulators ----
    float out0[16], out1[12], s1a[4];
    #pragma unroll
    for (int i = 0; i < 16; i++) out0[i] = 0.f;
    #pragma unroll
    for (int i = 0; i < 12; i++) out1[i] = 0.f;
    #pragma unroll
    for (int i = 0; i < 4; i++)  s1a[i] = 0.f;

    const float alpha = 0.15811388300841897f;         // 1/sqrt(40)
    const float cBc   = alpha * 0.57735026918962576f; // alpha/sqrt(3)
    const float* xr0 = xss + lr0 * X_ST;
    const float* xr1 = xss + (lr0 + 8) * X_ST;
    const float* b2s = reinterpret_cast<const float*>(smem + SM_BIAS);

    // epilogue for one 8-col tile (proven branch structure)
    auto epi = [&](int nt, int n8, const float* a) {
        const int coll = n8 * 8 + qid * 2;
        const float bv0 = b2s[nt * 128 + coll], bv1 = b2s[nt * 128 + coll + 1];
        const int gblk = nt * 16 + n8;
        #pragma unroll
        for (int e = 0; e < 2; e++) {
            const float* xr = e ? xr1 : xr0;
            const float v0 = a[e * 2 + 0] + bv0;
            const float v1 = a[e * 2 + 1] + bv1;
            if (gblk < 128) {                        // w00
                const int u = gblk >> 2;
                const float coeff = xr[u] * (alpha * xr[56]);
                const int o = e * 8 + (n8 & 3) * 2;
                out0[o + 0] = fmaf(coeff, v0, out0[o + 0]);
                out0[o + 1] = fmaf(coeff, v1, out0[o + 1]);
            } else if (gblk < 160) {                 // w11
                const int u = (gblk - 128) >> 2;
                const float du = xr[32 + u * 3 + 0] * xr[57]
                               + xr[32 + u * 3 + 1] * xr[58]
                               + xr[32 + u * 3 + 2] * xr[59];
                const float coeff = du * cBc;
                const int o = e * 8 + (n8 & 3) * 2;
                out0[o + 0] = fmaf(coeff, v0, out0[o + 0]);
                out0[o + 1] = fmaf(coeff, v1, out0[o + 1]);
            } else if (gblk < 192) {                 // w01 -> s1
                const float xu = xr[gblk - 160];
                s1a[e * 2 + 0] = fmaf(xu, v0, s1a[e * 2 + 0]);
                s1a[e * 2 + 1] = fmaf(xu, v1, s1a[e * 2 + 1]);
            } else {                                 // w10 -> out1
                const int u = gblk - 192;
                const float cy0 = alpha * xr[56];
                const float x0 = xr[32 + u * 3 + 0] * cy0;
                const float x1 = xr[32 + u * 3 + 1] * cy0;
                const float x2 = xr[32 + u * 3 + 2] * cy0;
                const int o = e * 6;
                out1[o + 0] = fmaf(x0, v0, out1[o + 0]);
                out1[o + 1] = fmaf(x1, v0, out1[o + 1]);
                out1[o + 2] = fmaf(x2, v0, out1[o + 2]);
                out1[o + 3] = fmaf(x0, v1, out1[o + 3]);
                out1[o + 4] = fmaf(x1, v1, out1[o + 4]);
                out1[o + 5] = fmaf(x2, v1, out1[o + 5]);
            }
        }
    };

    // ---- main loop over 13 N-tiles (proven) ----
    for (int nt = 0; nt < NT; nt++) {
        CP_WAIT1();
        __syncthreads();
        const uint32_t bufoff = (nt & 1) ? SM_B1 : SM_B0;
        const uint4* bp = reinterpret_cast<const uint4*>(smem + bufoff);
        const int npair = (nt == 12) ? 4 : 8;       // cols >= 1600 are padding

        for (int p = 0; p < npair; p++) {
            float a0[4] = {0.f, 0.f, 0.f, 0.f};
            float a1[4] = {0.f, 0.f, 0.f, 0.f};
            const uint4* f0p = bp + (2 * p) * 256 + lane;
            const uint4* f1p = bp + (2 * p + 1) * 256 + lane;
            #pragma unroll
            for (int ks = 0; ks < 8; ks++) {
                const uint4 f0 = f0p[ks * 32];
                const uint4 f1 = f1p[ks * 32];
                mma16816(a0, afh[ks], f0.x, f0.y);
                mma16816(a1, afh[ks], f1.x, f1.y);
                mma16816(a0, afh[ks], f0.z, f0.w);
                mma16816(a1, afh[ks], f1.z, f1.w);
                mma16816(a0, afl[ks], f0.x, f0.y);
                mma16816(a1, afl[ks], f1.x, f1.y);
            }
            epi(nt, 2 * p,     a0);
            epi(nt, 2 * p + 1, a1);
        }
        __syncthreads();
        if (nt + 2 < NT) loadPK(nt + 2, sb + bufoff);
        CP_COMMIT();
    }

    // ---- fold w01 path, scatter ----
    #pragma unroll
    for (int e = 0; e < 2; e++) {
        const float* xr = e ? xr1 : xr0;
        if (!reinterpret_cast<const int*>(xr)[61]) continue;
        const int srcn = reinterpret_cast<const int*>(xr)[60];
        const float yx = xr[57], yy = xr[58], yz = xr[59];
        #pragma unroll
        for (int p = 0; p < 2; p++) {
            const float sw = s1a[e * 2 + p] * alpha;
            out1[e * 6 + p * 3 + 0] = fmaf(sw, yx, out1[e * 6 + p * 3 + 0]);
            out1[e * 6 + p * 3 + 1] = fmaf(sw, yy, out1[e * 6 + p * 3 + 1]);
            out1[e * 6 + p * 3 + 2] = fmaf(sw, yz, out1[e * 6 + p * 3 + 2]);
        }
        float* dstp = g_num + (size_t)srcn * IN_DIM;
        #pragma unroll
        for (int q = 0; q < 4; q++)
            #pragma unroll
            for (int p = 0; p < 2; p++) {
                const int w = q * 8 + qid * 2 + p;
                atomicAdd(&dstp[w], out0[e * 8 + q * 2 + p]);
            }
        #pragma unroll
        for (int p = 0; p < 2; p++) {
            const int w8 = qid * 2 + p;
            atomicAdd(&dstp[32 + w8 * 3 + 0], out1[e * 6 + p * 3 + 0]);
            atomicAdd(&dstp[32 + w8 * 3 + 1], out1[e * 6 + p * 3 + 1]);
            atomicAdd(&dstp[32 + w8 * 3 + 2], out1[e * 6 + p * 3 + 2]);
        }
        if (qid == 0) atomicAdd(&g_cnt[srcn], 1.0f);
    }
}

// ==================================================================
// finalize 1 (parallel): thread (channel, m) accumulates over 20 nodes
// ==================================================================
#define F1_NPC 80
#define F1_GRID ((N_NODES + F1_NPC - 1) / F1_NPC)   // 125

__global__ void finalize1_kernel(const float* __restrict__ node_attr,
                                 float* __restrict__ staged) {
    __shared__ float s_stats[72];
    const int tid = threadIdx.x;
    if (tid < 72) s_stats[tid] = 0.f;
    __syncthreads();

    const int c = tid & 63;           // channel (0..55 active)
    const int m = tid >> 6;           // 0..3
    if (c < IN_DIM) {
        float sum = 0.f, sum2 = 0.f;
        const int nbase = blockIdx.x * F1_NPC + m * (F1_NPC / 4);
        #pragma unroll 4
        for (int k = 0; k < F1_NPC / 4; k++) {
            const int n = nbase + k;
            if (n < N_NODES) {
                const float ic = 1.f / fmaxf(g_cnt[n], 1.f);
                const float o = g_num[(size_t)n * IN_DIM + c] * ic
                              + node_attr[(size_t)n * IN_DIM + c];
                staged[(size_t)n * IN_DIM + c] = o;
                sum += o; sum2 += o * o;
            }
        }
        if (c < 32) {
            atomicAdd(&s_stats[c], sum);
            atomicAdd(&s_stats[32 + c], sum2);
        } else {
            atomicAdd(&s_stats[64 + (c - 32) / 3], sum2);
        }
    }
    __syncthreads();
    if (tid < 72) atomicAdd(&g_stats[tid], s_stats[tid]);
}

// ==================================================================
// finalize 2: batch norm in place on d_out
// ==================================================================
__global__ void finalize2_kernel(const float* __restrict__ bn_w_s,
                                 const float* __restrict__ bn_w_v,
                                 const float* __restrict__ bn_b_s,
                                 float* __restrict__ out) {
    const int idx = blockIdx.x * blockDim.x + threadIdx.x;
    if (idx >= N_NODES * IN_DIM) return;
    const int j = idx % IN_DIM;
    const float x = out[idx];
    const float invN = 1.0f / (float)N_NODES;
    if (j < 32) {
        float mean = g_stats[j] * invN;
        float var  = g_stats[32 + j] * invN - mean * mean;
        out[idx] = (x - mean) * rsqrtf(var + 1e-5f) * bn_w_s[j] + bn_b_s[j];
    } else {
        int u = (j - 32) / 3;
        float vn = g_stats[64 + u] * invN * (1.0f / 3.0f);
        out[idx] = x * rsqrtf(vn + 1e-5f) * bn_w_v[u];
    }
}

// ==================================================================
extern "C" void kernel_launch(void* const* d_in, const int* in_sizes, int n_in,
                              void* d_out, int out_size) {
    const float* node_attr  = (const float*)d_in[0];
    const int*   edge_index = (const int*)d_in[1];
    const float* edge_attr  = (const float*)d_in[2];
    const float* edge_sh    = (const float*)d_in[3];
    const float* fc1_w      = (const float*)d_in[4];
    const float* fc1_b      = (const float*)d_in[5];
    const float* fc2_w      = (const float*)d_in[6];
    const float* fc2_b      = (const float*)d_in[7];
    const float* bn_w_s     = (const float*)d_in[8];
    const float* bn_w_v     = (const float*)d_in[9];
    const float* bn_b_s     = (const float*)d_in[10];
    float* out = (float*)d_out;

    cudaFuncSetAttribute(fused_kernel,
                         cudaFuncAttributeMaxDynamicSharedMemorySize, SMEM_SZ);

    setup_kernel<<<(SETUP_TOTAL + 255) / 256, 256>>>(fc2_w, fc1_w);
    fused_kernel<<<GRID2, 512, SMEM_SZ>>>(node_attr, edge_index, edge_sh,
                                          edge_attr, fc1_b, fc2_b);
    finalize1_kernel<<<F1_GRID, 256>>>(node_attr, out);
    finalize2_kernel<<<(N_NODES * IN_DIM + 255) / 256, 256>>>(bn_w_s, bn_w_v, bn_b_s, out);
}

// round 17
// speedup vs baseline: 1.9588x; 1.2719x over previous
#include <cuda_runtime.h>
#include <cuda_fp16.h>
#include <cuda_bf16.h>
#include <stdint.h>

#define N_NODES 10000
#define N_EDGES 100000
#define HIDDEN  128
#define WN      1600
#define IN_DIM  56
#define NT      13
#define EPC2    256                            // edges per CTA
#define GRID2   ((N_EDGES + EPC2 - 1) / EPC2)  // 391

// ---- scratch (static __device__; aligned for cp.async 16B) ----
// packed fp16 B fragments: one uint4 covers TWO n8 columns (pair), one ks
// idx = ((nt*8 + P)*8 + ks)*32 + lane ; n_a = nt*128 + 2P*8 + lane/4, n_b = n_a+8
// k = ks*16 + (lane%4)*2 ; uint4 = { Ba(k,k+1), Ba(k+8,k+9), Bb(k,k+1), Bb(k+8,k+9) }
__device__ __align__(256) uint4 g_B2pk[NT * 2048];
__device__ __align__(256) uint4 g_B1pk[2048];
__device__ __align__(256) float g_num[(size_t)N_NODES * IN_DIM];
__device__ __align__(256) float g_cnt[N_NODES];
__device__ __align__(256) float g_stats[72];

// ==================================================================
// PTX helpers
// ==================================================================
__device__ __forceinline__ uint32_t smem_u32(const void* p) {
    uint32_t a;
    asm("{ .reg .u64 t; cvta.to.shared.u64 t, %1; cvt.u32.u64 %0, t; }"
        : "=r"(a) : "l"(p));
    return a;
}
__device__ __forceinline__ void mma16816h(float* c, const uint32_t* a,
                                          uint32_t b0, uint32_t b1) {
    asm volatile(
        "mma.sync.aligned.m16n8k16.row.col.f32.f16.f16.f32 "
        "{%0,%1,%2,%3}, {%4,%5,%6,%7}, {%8,%9}, {%0,%1,%2,%3};"
        : "+f"(c[0]), "+f"(c[1]), "+f"(c[2]), "+f"(c[3])
        : "r"(a[0]), "r"(a[1]), "r"(a[2]), "r"(a[3]), "r"(b0), "r"(b1));
}
__device__ __forceinline__ void cp16(uint32_t dst, const void* src) {
    asm volatile("cp.async.cg.shared.global [%0], [%1], 16;" :: "r"(dst), "l"(src));
}
#define CP_COMMIT() asm volatile("cp.async.commit_group;" ::: "memory")
#define CP_WAIT0()  asm volatile("cp.async.wait_group 0;" ::: "memory")
#define CP_WAIT1()  asm volatile("cp.async.wait_group 1;" ::: "memory")

__device__ __forceinline__ uint32_t pack_h2(float v0, float v1) {
    __half2 h = __floats2half2_rn(v0, v1);
    return *reinterpret_cast<uint32_t*>(&h);
}
// A-split: Ah = fp16(x), Al = fp16(x - Ah); Ah+Al represents x to ~2^-22
__device__ __forceinline__ void split_pair_f16(float v0, float v1,
                                               uint32_t& hi, uint32_t& lo) {
    __half h0 = __float2half_rn(v0), h1 = __float2half_rn(v1);
    __half2 hh = __halves2half2(h0, h1);
    hi = *reinterpret_cast<uint32_t*>(&hh);
    lo = pack_h2(v0 - __half2float(h0), v1 - __half2float(h1));
}

// ==================================================================
// setup: zero accumulators + pack fc1/fc2 fp16 fragments (ONE launch)
// destinations referenced as device symbols IN DEVICE CODE only.
// ==================================================================
__global__ void setup_kernel(const float* __restrict__ fc2_w,
                             const float* __restrict__ fc1_w) {
    int i = blockIdx.x * blockDim.x + threadIdx.x;
    const int z0 = N_NODES * IN_DIM;
    const int z1 = z0 + N_NODES;
    const int z2 = z1 + 72;
    const int p2 = z2 + NT * 2048;
    const int p1 = p2 + 2048;
    if (i < z0) { g_num[i] = 0.f; return; }
    if (i < z1) { g_cnt[i - z0] = 0.f; return; }
    if (i < z2) { g_stats[i - z1] = 0.f; return; }
    if (i >= p1) return;

    const bool isB1 = (i >= p2);
    const int idx = isB1 ? (i - p2) : (i - z2);
    const float* src = isB1 ? fc1_w : fc2_w;
    const int nvalid = isB1 ? 128 : WN;
    const int ld     = isB1 ? 128 : WN;
    uint4* dst = isB1 ? g_B1pk : g_B2pk;

    int lane = idx & 31;
    int ks   = (idx >> 5) & 7;
    int P    = (idx >> 8) & 7;
    int nt   = idx >> 11;
    int n_a = nt * 128 + P * 16 + (lane >> 2);
    int n_b = n_a + 8;
    int k = ks * 16 + (lane & 3) * 2;
    float a0 = 0.f, a1 = 0.f, a2 = 0.f, a3 = 0.f;
    float b0 = 0.f, b1 = 0.f, b2 = 0.f, b3 = 0.f;
    if (n_a < nvalid) {
        a0 = src[(size_t)k * ld + n_a];
        a1 = src[(size_t)(k + 1) * ld + n_a];
        a2 = src[(size_t)(k + 8) * ld + n_a];
        a3 = src[(size_t)(k + 9) * ld + n_a];
    }
    if (n_b < nvalid) {
        b0 = src[(size_t)k * ld + n_b];
        b1 = src[(size_t)(k + 1) * ld + n_b];
        b2 = src[(size_t)(k + 8) * ld + n_b];
        b3 = src[(size_t)(k + 9) * ld + n_b];
    }
    dst[idx] = make_uint4(pack_h2(a0, a1), pack_h2(a2, a3),
                          pack_h2(b0, b1), pack_h2(b2, b3));
}
#define SETUP_TOTAL (N_NODES * IN_DIM + N_NODES + 72 + NT * 2048 + 2048)

// ==================================================================
// FUSED: H = relu(edge_attr@fc1+b1) in regs -> W = H@fc2+b2 -> TP -> scatter
// 512 threads (16 warps), 256 edges/CTA. fp16 2-term (exact-A, trunc-B).
// ==================================================================
#define SM_B0    0         // staging rows 0..127 (64KB); later: even tiles (32KB)
#define SM_B1    65536     // staging rows 128..255; odd tiles at T1 below
#define T0       0
#define T1       32768
#define SM_X     131072    // 256 * 62 * 4 = 63488
#define X_ST     62
#define SM_BIAS  194560    // fc2_b: 416 uint4 = 6656
#define SM_BIAS1 201216    // fc1_b: 512
#define SMEM_SZ  201728

__global__ void __launch_bounds__(512, 1)
fused_kernel(const float* __restrict__ node_attr,
             const int*   __restrict__ edge_index,
             const float* __restrict__ edge_sh,
             const float* __restrict__ edge_attr,
             const float* __restrict__ fc1_b,
             const float* __restrict__ fc2_b) {
    extern __shared__ char smem[];
    const uint32_t sb = smem_u32(smem);
    const int tid = threadIdx.x, warp = tid >> 5, lane = tid & 31;
    const int gid = lane >> 2, qid = lane & 3;
    const int bm = blockIdx.x * EPC2;
    const int lr0 = warp * 16 + gid;          // 0..255

    // ---- stage edge_attr fp32: rows 0..127 -> B0, 128..255 -> B1 ----
    for (int i = tid; i < 8192; i += 512) {
        int r = i >> 5, q = i & 31;
        int gr = bm + r;
        uint32_t doff = (r < 128 ? SM_B0 + r * 512 : SM_B1 + (r - 128) * 512)
                      + (uint32_t)q * 16;
        if (gr < N_EDGES)
            cp16(sb + doff, edge_attr + (size_t)gr * 128 + q * 4);
        else
            *reinterpret_cast<uint4*>(smem + doff) = make_uint4(0u, 0u, 0u, 0u);
    }
    // ---- biases ----
    for (int i = tid; i < 416; i += 512) {
        if (i < 400) cp16(sb + SM_BIAS + i * 16, fc2_b + i * 4);
        else *reinterpret_cast<uint4*>(smem + SM_BIAS + i * 16) = make_uint4(0u, 0u, 0u, 0u);
    }
    if (tid < 32) cp16(sb + SM_BIAS1 + tid * 16, fc1_b + tid * 4);
    // ---- per-edge features ----
    float* xss = reinterpret_cast<float*>(smem + SM_X);
    if (tid < EPC2) {
        const int e = bm + tid;
        const bool valid = (e < N_EDGES);
        float* xr = xss + tid * X_ST;
        int dst = valid ? edge_index[N_EDGES + e] : 0;
        for (int j = 0; j < IN_DIM; j++)
            xr[j] = valid ? node_attr[(size_t)dst * IN_DIM + j] : 0.f;
        float y0 = 0.f, yx = 0.f, yy = 0.f, yz = 0.f;
        int srcn = 0;
        if (valid) {
            srcn = edge_index[e];
            y0 = edge_sh[e * 4 + 0]; yx = edge_sh[e * 4 + 1];
            yy = edge_sh[e * 4 + 2]; yz = edge_sh[e * 4 + 3];
        }
        xr[56] = y0; xr[57] = yx; xr[58] = yy; xr[59] = yz;
        reinterpret_cast<int*>(xr)[60] = srcn;
        reinterpret_cast<int*>(xr)[61] = valid ? 1 : 0;
    }
    CP_COMMIT();
    CP_WAIT0();
    __syncthreads();

    // ---- GEMM1: Hacc = edge_attr @ fc1 (fp16 2-term, B fragments via LDG) ----
    float Hacc[16][4];
    #pragma unroll
    for (int i = 0; i < 16; i++)
        #pragma unroll
        for (int j = 0; j < 4; j++) Hacc[i][j] = 0.f;
    {
        const float* Arow0 = reinterpret_cast<const float*>(
            smem + (lr0 < 128 ? SM_B0 + lr0 * 512 : SM_B1 + (lr0 - 128) * 512));
        const float* Arow1 = Arow0 + 8 * 128;   // row lr0+8, same buffer
        for (int ks = 0; ks < 8; ks++) {        // not unrolled: bound regs
            int c = ks * 16 + qid * 2;
            float2 v00 = *reinterpret_cast<const float2*>(Arow0 + c);
            float2 v10 = *reinterpret_cast<const float2*>(Arow1 + c);
            float2 v01 = *reinterpret_cast<const float2*>(Arow0 + c + 8);
            float2 v11 = *reinterpret_cast<const float2*>(Arow1 + c + 8);
            uint32_t ah[4], al[4];
            split_pair_f16(v00.x, v00.y, ah[0], al[0]);
            split_pair_f16(v10.x, v10.y, ah[1], al[1]);
            split_pair_f16(v01.x, v01.y, ah[2], al[2]);
            split_pair_f16(v11.x, v11.y, ah[3], al[3]);
            const uint4* fp = g_B1pk + ks * 32 + lane;
            #pragma unroll
            for (int P = 0; P < 8; P++) {
                const uint4 f = fp[P * 256];     // (P*8+ks)*32+lane
                mma16816h(Hacc[2 * P],     ah, f.x, f.y);
                mma16816h(Hacc[2 * P + 1], ah, f.z, f.w);
                mma16816h(Hacc[2 * P],     al, f.x, f.y);
                mma16816h(Hacc[2 * P + 1], al, f.z, f.w);
            }
        }
    }
    // ---- H epilogue: bias + relu -> exact fp16 split -> GEMM2 A fragments ----
    uint32_t afh[8][4], afl[8][4];
    {
        const float* b1s = reinterpret_cast<const float*>(smem + SM_BIAS1);
        #pragma unroll
        for (int n8 = 0; n8 < 16; n8++) {
            int col = n8 * 8 + qid * 2;
            float b0 = b1s[col], b1v = b1s[col + 1];
            float v0 = fmaxf(Hacc[n8][0] + b0, 0.f);
            float v1 = fmaxf(Hacc[n8][1] + b1v, 0.f);
            float v2 = fmaxf(Hacc[n8][2] + b0, 0.f);
            float v3 = fmaxf(Hacc[n8][3] + b1v, 0.f);
            int ks2 = n8 >> 1, idx = (n8 & 1) * 2;
            split_pair_f16(v0, v1, afh[ks2][idx],     afl[ks2][idx]);
            split_pair_f16(v2, v3, afh[ks2][idx + 1], afl[ks2][idx + 1]);
        }
    }
    __syncthreads();   // edge_attr staging fully consumed; buffers free

    // ---- prefetch packed B2 tiles 0, 1 (32KB each) ----
    auto loadPK = [&](int nt, uint32_t base) {
        const uint4* srcp = g_B2pk + nt * 2048;
        for (int i = tid; i < 2048; i += 512)
            cp16(base + (uint32_t)i * 16, srcp + i);
    };
    loadPK(0, sb + T0); CP_COMMIT();
    loadPK(1, sb + T1); CP_COMMIT();

    // ---- TP accumulators ----
    float out0[16], out1[12], s1a[4];
    #pragma unroll
    for (int i = 0; i < 16; i++) out0[i] = 0.f;
    #pragma unroll
    for (int i = 0; i < 12; i++) out1[i] = 0.f;
    #pragma unroll
    for (int i = 0; i < 4; i++)  s1a[i] = 0.f;

    const float alpha = 0.15811388300841897f;         // 1/sqrt(40)
    const float cBc   = alpha * 0.57735026918962576f; // alpha/sqrt(3)
    const float* xr0 = xss + lr0 * X_ST;
    const float* xr1 = xss + (lr0 + 8) * X_ST;
    const float* b2s = reinterpret_cast<const float*>(smem + SM_BIAS);

    // epilogue for one 8-col tile (proven branch structure)
    auto epi = [&](int nt, int n8, const float* a) {
        const int coll = n8 * 8 + qid * 2;
        const float bv0 = b2s[nt * 128 + coll], bv1 = b2s[nt * 128 + coll + 1];
        const int gblk = nt * 16 + n8;
        #pragma unroll
        for (int e = 0; e < 2; e++) {
            const float* xr = e ? xr1 : xr0;
            const float v0 = a[e * 2 + 0] + bv0;
            const float v1 = a[e * 2 + 1] + bv1;
            if (gblk < 128) {                        // w00
                const int u = gblk >> 2;
                const float coeff = xr[u] * (alpha * xr[56]);
                const int o = e * 8 + (n8 & 3) * 2;
                out0[o + 0] = fmaf(coeff, v0, out0[o + 0]);
                out0[o + 1] = fmaf(coeff, v1, out0[o + 1]);
            } else if (gblk < 160) {                 // w11
                const int u = (gblk - 128) >> 2;
                const float du = xr[32 + u * 3 + 0] * xr[57]
                               + xr[32 + u * 3 + 1] * xr[58]
                               + xr[32 + u * 3 + 2] * xr[59];
                const float coeff = du * cBc;
                const int o = e * 8 + (n8 & 3) * 2;
                out0[o + 0] = fmaf(coeff, v0, out0[o + 0]);
                out0[o + 1] = fmaf(coeff, v1, out0[o + 1]);
            } else if (gblk < 192) {                 // w01 -> s1
                const float xu = xr[gblk - 160];
                s1a[e * 2 + 0] = fmaf(xu, v0, s1a[e * 2 + 0]);
                s1a[e * 2 + 1] = fmaf(xu, v1, s1a[e * 2 + 1]);
            } else {                                 // w10 -> out1
                const int u = gblk - 192;
                const float cy0 = alpha * xr[56];
                const float x0 = xr[32 + u * 3 + 0] * cy0;
                const float x1 = xr[32 + u * 3 + 1] * cy0;
                const float x2 = xr[32 + u * 3 + 2] * cy0;
                const int o = e * 6;
                out1[o + 0] = fmaf(x0, v0, out1[o + 0]);
                out1[o + 1] = fmaf(x1, v0, out1[o + 1]);
                out1[o + 2] = fmaf(x2, v0, out1[o + 2]);
                out1[o + 3] = fmaf(x0, v1, out1[o + 3]);
                out1[o + 4] = fmaf(x1, v1, out1[o + 4]);
                out1[o + 5] = fmaf(x2, v1, out1[o + 5]);
            }
        }
    };

    // ---- main loop over 13 N-tiles: 1 LDS.128 -> 4 MMAs ----
    for (int nt = 0; nt < NT; nt++) {
        CP_WAIT1();
        __syncthreads();
        const uint32_t bufoff = (nt & 1) ? T1 : T0;
        const uint4* bp = reinterpret_cast<const uint4*>(smem + bufoff);
        const int npair = (nt == 12) ? 4 : 8;       // cols >= 1600 are padding

        for (int p = 0; p < npair; p++) {
            float a0[4] = {0.f, 0.f, 0.f, 0.f};
            float a1[4] = {0.f, 0.f, 0.f, 0.f};
            const uint4* fp = bp + p * 256 + lane;   // (p*8+ks)*32+lane
            #pragma unroll
            for (int ks = 0; ks < 8; ks++) {
                const uint4 f = fp[ks * 32];
                mma16816h(a0, afh[ks], f.x, f.y);
                mma16816h(a1, afh[ks], f.z, f.w);
                mma16816h(a0, afl[ks], f.x, f.y);
                mma16816h(a1, afl[ks], f.z, f.w);
            }
            epi(nt, 2 * p,     a0);
            epi(nt, 2 * p + 1, a1);
        }
        __syncthreads();
        if (nt + 2 < NT) loadPK(nt + 2, sb + bufoff);
        CP_COMMIT();
    }

    // ---- fold w01 path, scatter ----
    #pragma unroll
    for (int e = 0; e < 2; e++) {
        const float* xr = e ? xr1 : xr0;
        if (!reinterpret_cast<const int*>(xr)[61]) continue;
        const int srcn = reinterpret_cast<const int*>(xr)[60];
        const float yx = xr[57], yy = xr[58], yz = xr[59];
        #pragma unroll
        for (int p = 0; p < 2; p++) {
            const float sw = s1a[e * 2 + p] * alpha;
            out1[e * 6 + p * 3 + 0] = fmaf(sw, yx, out1[e * 6 + p * 3 + 0]);
            out1[e * 6 + p * 3 + 1] = fmaf(sw, yy, out1[e * 6 + p * 3 + 1]);
            out1[e * 6 + p * 3 + 2] = fmaf(sw, yz, out1[e * 6 + p * 3 + 2]);
        }
        float* dstp = g_num + (size_t)srcn * IN_DIM;
        #pragma unroll
        for (int q = 0; q < 4; q++)
            #pragma unroll
            for (int p = 0; p < 2; p++) {
                const int w = q * 8 + qid * 2 + p;
                atomicAdd(&dstp[w], out0[e * 8 + q * 2 + p]);
            }
        #pragma unroll
        for (int p = 0; p < 2; p++) {
            const int w8 = qid * 2 + p;
            atomicAdd(&dstp[32 + w8 * 3 + 0], out1[e * 6 + p * 3 + 0]);
            atomicAdd(&dstp[32 + w8 * 3 + 1], out1[e * 6 + p * 3 + 1]);
            atomicAdd(&dstp[32 + w8 * 3 + 2], out1[e * 6 + p * 3 + 2]);
        }
        if (qid == 0) atomicAdd(&g_cnt[srcn], 1.0f);
    }
}

// ==================================================================
// finalize 1 (parallel): thread (channel, m) accumulates over 20 nodes
// ==================================================================
#define F1_NPC 80
#define F1_GRID ((N_NODES + F1_NPC - 1) / F1_NPC)   // 125

__global__ void finalize1_kernel(const float* __restrict__ node_attr,
                                 float* __restrict__ staged) {
    __shared__ float s_stats[72];
    const int tid = threadIdx.x;
    if (tid < 72) s_stats[tid] = 0.f;
    __syncthreads();

    const int c = tid & 63;           // channel (0..55 active)
    const int m = tid >> 6;           // 0..3
    if (c < IN_DIM) {
        float sum = 0.f, sum2 = 0.f;
        const int nbase = blockIdx.x * F1_NPC + m * (F1_NPC / 4);
        #pragma unroll 4
        for (int k = 0; k < F1_NPC / 4; k++) {
            const int n = nbase + k;
            if (n < N_NODES) {
                const float ic = 1.f / fmaxf(g_cnt[n], 1.f);
                const float o = g_num[(size_t)n * IN_DIM + c] * ic
                              + node_attr[(size_t)n * IN_DIM + c];
                staged[(size_t)n * IN_DIM + c] = o;
                sum += o; sum2 += o * o;
            }
        }
        if (c < 32) {
            atomicAdd(&s_stats[c], sum);
            atomicAdd(&s_stats[32 + c], sum2);
        } else {
            atomicAdd(&s_stats[64 + (c - 32) / 3], sum2);
        }
    }
    __syncthreads();
    if (tid < 72) atomicAdd(&g_stats[tid], s_stats[tid]);
}

// ==================================================================
// finalize 2: batch norm in place on d_out
// ==================================================================
__global__ void finalize2_kernel(const float* __restrict__ bn_w_s,
                                 const float* __restrict__ bn_w_v,
                                 const float* __restrict__ bn_b_s,
                                 float* __restrict__ out) {
    const int idx = blockIdx.x * blockDim.x + threadIdx.x;
    if (idx >= N_NODES * IN_DIM) return;
    const int j = idx % IN_DIM;
    const float x = out[idx];
    const float invN = 1.0f / (float)N_NODES;
    if (j < 32) {
        float mean = g_stats[j] * invN;
        float var  = g_stats[32 + j] * invN - mean * mean;
        out[idx] = (x - mean) * rsqrtf(var + 1e-5f) * bn_w_s[j] + bn_b_s[j];
    } else {
        int u = (j - 32) / 3;
        float vn = g_stats[64 + u] * invN * (1.0f / 3.0f);
        out[idx] = x * rsqrtf(vn + 1e-5f) * bn_w_v[u];
    }
}

// ==================================================================
extern "C" void kernel_launch(void* const* d_in, const int* in_sizes, int n_in,
                              void* d_out, int out_size) {
    const float* node_attr  = (const float*)d_in[0];
    const int*   edge_index = (const int*)d_in[1];
    const float* edge_attr  = (const float*)d_in[2];
    const float* edge_sh    = (const float*)d_in[3];
    const float* fc1_w      = (const float*)d_in[4];
    const float* fc1_b      = (const float*)d_in[5];
    const float* fc2_w      = (const float*)d_in[6];
    const float* fc2_b      = (const float*)d_in[7];
    const float* bn_w_s     = (const float*)d_in[8];
    const float* bn_w_v     = (const float*)d_in[9];
    const float* bn_b_s     = (const float*)d_in[10];
    float* out = (float*)d_out;

    cudaFuncSetAttribute(fused_kernel,
                         cudaFuncAttributeMaxDynamicSharedMemorySize, SMEM_SZ);

    setup_kernel<<<(SETUP_TOTAL + 255) / 256, 256>>>(fc2_w, fc1_w);
    fused_kernel<<<GRID2, 512, SMEM_SZ>>>(node_attr, edge_index, edge_sh,
                                          edge_attr, fc1_b, fc2_b);
    finalize1_kernel<<<F1_GRID, 256>>>(node_attr, out);
    finalize2_kernel<<<(N_NODES * IN_DIM + 255) / 256, 256>>>(bn_w_s, bn_w_v, bn_b_s, out);
}